// round 1
// baseline (speedup 1.0000x reference)
#include <cuda_runtime.h>
#include <cstdint>

#define N_IN    16
#define N_MF    2
#define N_RULES 64
#define NPAIR   32        // rule pairs (f32x2 lanes)
#define TPB     256

// ---------- f32x2 helpers (sm_100a packed fp32) ----------
__device__ __forceinline__ unsigned long long pack2(float lo, float hi) {
    unsigned long long r;
    asm("mov.b64 %0, {%1, %2};" : "=l"(r) : "f"(lo), "f"(hi));
    return r;
}
__device__ __forceinline__ void unpack2(unsigned long long v, float& lo, float& hi) {
    asm("mov.b64 {%0, %1}, %2;" : "=f"(lo), "=f"(hi) : "l"(v));
}
__device__ __forceinline__ unsigned long long ffma2(unsigned long long a,
                                                    unsigned long long b,
                                                    unsigned long long c) {
    unsigned long long d;
    asm("fma.rn.f32x2 %0, %1, %2, %3;" : "=l"(d) : "l"(a), "l"(b), "l"(c));
    return d;
}
__device__ __forceinline__ unsigned long long fadd2(unsigned long long a,
                                                    unsigned long long b) {
    unsigned long long d;
    asm("add.rn.f32x2 %0, %1, %2;" : "=l"(d) : "l"(a), "l"(b));
    return d;
}
__device__ __forceinline__ unsigned long long fmul2(unsigned long long a,
                                                    unsigned long long b) {
    unsigned long long d;
    asm("mul.rn.f32x2 %0, %1, %2;" : "=l"(d) : "l"(a), "l"(b));
    return d;
}
__device__ __forceinline__ float ex2_fast(float x) {
    float y;
    asm("ex2.approx.f32 %0, %1;" : "=f"(y) : "f"(x));
    return y;
}

__device__ __forceinline__ unsigned long long ld_sh2(const float2* p) {
    return *reinterpret_cast<const unsigned long long*>(p);
}

// -0.5 * log2(e), 1/ln(2)
#define NEG_HALF_LOG2E (-0.7213475204444817f)
#define LOG2E          ( 1.4426950408889634f)

__global__ __launch_bounds__(TPB)
void anfis_kernel(const float* __restrict__ x,          // [B,16]
                  const float* __restrict__ center,     // [16,2]
                  const float* __restrict__ log_sigma,  // [16,2]
                  const float* __restrict__ consequent, // [64,17]
                  const int*   __restrict__ rule_idx,   // [64,16]
                  const float* __restrict__ amask,      // [64]
                  float* __restrict__ out, int B)
{
    // Shared, pre-packed per rule-pair p = (rule 2p, rule 2p+1)
    __shared__ float2 s_mask[N_IN][NPAIR];      // (bit(2p,i), bit(2p+1,i)) as 0.0/1.0
    __shared__ float2 s_cons[N_IN + 1][NPAIR];  // (C[2p][i], C[2p+1][i]); i==16 is bias
    __shared__ float2 s_am[NPAIR];              // active_mask pairs
    __shared__ float2 s_fb[NPAIR];              // fallback weight pairs
    __shared__ float  s_cen[N_IN][N_MF];
    __shared__ float  s_inv[N_IN][N_MF];        // 1/(exp(log_sigma)+1e-6)

    const int tid = threadIdx.x;

    for (int idx = tid; idx < N_IN * NPAIR; idx += TPB) {
        int i = idx >> 5, p = idx & 31;
        float m0 = (float)rule_idx[(2 * p)     * N_IN + i];
        float m1 = (float)rule_idx[(2 * p + 1) * N_IN + i];
        s_mask[i][p] = make_float2(m0, m1);
    }
    for (int idx = tid; idx < (N_IN + 1) * NPAIR; idx += TPB) {
        int i = idx >> 5, p = idx & 31;
        s_cons[i][p] = make_float2(consequent[(2 * p)     * (N_IN + 1) + i],
                                   consequent[(2 * p + 1) * (N_IN + 1) + i]);
    }
    if (tid < N_IN * N_MF) {
        int i = tid >> 1, j = tid & 1;
        s_cen[i][j] = center[i * N_MF + j];
        s_inv[i][j] = 1.0f / (expf(log_sigma[i * N_MF + j]) + 1e-6f);
    }
    if (tid < NPAIR) {
        float asum = 0.f;
        #pragma unroll
        for (int r = 0; r < N_RULES; r++) asum += amask[r];
        float inv = 1.0f / fmaxf(asum, 1.0f);
        float a0 = amask[2 * tid], a1 = amask[2 * tid + 1];
        s_am[tid] = make_float2(a0, a1);
        s_fb[tid] = make_float2(a0 * inv, a1 * inv);
    }
    __syncthreads();

    const int row = blockIdx.x * TPB + tid;
    if (row >= B) return;

    // ---- load x row (4 x float4, 64B/thread) ----
    const float4* xv = reinterpret_cast<const float4*>(x + (size_t)row * N_IN);
    float4 v0 = xv[0], v1 = xv[1], v2 = xv[2], v3 = xv[3];
    float xr[N_IN] = {v0.x, v0.y, v0.z, v0.w, v1.x, v1.y, v1.z, v1.w,
                      v2.x, v2.y, v2.z, v2.w, v3.x, v3.y, v3.z, v3.w};

    // ---- membership in log2 space: base + bitmask-selected diffs ----
    float base = 0.f;
    unsigned long long diff2[N_IN], x2[N_IN];
    #pragma unroll
    for (int i = 0; i < N_IN; i++) {
        float d0 = (xr[i] - s_cen[i][0]) * s_inv[i][0];
        float d1 = (xr[i] - s_cen[i][1]) * s_inv[i][1];
        float l0 = d0 * d0 * NEG_HALF_LOG2E;
        float l1 = d1 * d1 * NEG_HALF_LOG2E;
        base += l0;
        float df = l1 - l0;
        diff2[i] = pack2(df, df);
        x2[i]    = pack2(xr[i], xr[i]);
    }
    const unsigned long long base2 = pack2(base, base);

    unsigned long long fs2  = 0ull;  // (0,0): sum of firing
    unsigned long long acc2 = 0ull;  // sum firing * rule_out
    unsigned long long fb2  = 0ull;  // sum fallback * rule_out

    #pragma unroll 4
    for (int p = 0; p < NPAIR; p++) {
        // t = base + sum_i bit * diff   (log2 of firing, per rule pair)
        unsigned long long t2 = base2;
        #pragma unroll
        for (int i = 0; i < N_IN; i++)
            t2 = ffma2(diff2[i], ld_sh2(&s_mask[i][p]), t2);

        float tlo, thi;
        unpack2(t2, tlo, thi);
        unsigned long long f2 = pack2(ex2_fast(tlo), ex2_fast(thi));
        f2  = fmul2(f2, ld_sh2(&s_am[p]));
        fs2 = fadd2(fs2, f2);

        // rule_out pair: bias + sum_i x_i * C[r][i]
        unsigned long long ro2 = ld_sh2(&s_cons[N_IN][p]);
        #pragma unroll
        for (int i = 0; i < N_IN; i++)
            ro2 = ffma2(x2[i], ld_sh2(&s_cons[i][p]), ro2);

        acc2 = ffma2(f2, ro2, acc2);
        fb2  = ffma2(ld_sh2(&s_fb[p]), ro2, fb2);
    }

    float fsl, fsh, al, ah, fl, fh;
    unpack2(fs2, fsl, fsh);
    unpack2(acc2, al, ah);
    unpack2(fb2, fl, fh);
    float fs  = fsl + fsh;
    float acc = al + ah;
    float fbk = fl + fh;

    float z = (fs <= 1e-12f) ? fbk : __fdividef(acc, fs);

    // sigmoid + clip
    float s = __fdividef(1.0f, 1.0f + ex2_fast(-z * LOG2E));
    s = fminf(fmaxf(s, 1e-7f), 1.0f - 1e-7f);
    out[row] = s;
}

extern "C" void kernel_launch(void* const* d_in, const int* in_sizes, int n_in,
                              void* d_out, int out_size)
{
    const float* x          = (const float*)d_in[0];
    const float* center     = (const float*)d_in[1];
    const float* log_sigma  = (const float*)d_in[2];
    const float* consequent = (const float*)d_in[3];
    const int*   rule_idx   = (const int*)  d_in[4];
    const float* amask      = (const float*)d_in[5];
    float*       out        = (float*)d_out;

    int B = in_sizes[0] / N_IN;
    int grid = (B + TPB - 1) / TPB;
    anfis_kernel<<<grid, TPB>>>(x, center, log_sigma, consequent, rule_idx,
                                amask, out, B);
}